// round 2
// baseline (speedup 1.0000x reference)
#include <cuda_runtime.h>

// DigitCaps dynamic routing, fused. B=64, R=6912, I=8, C=10, O=16, 3 iters.
//
// Launch sequence (graph-capturable, 4 kernels):
//   k_transpose : x[B,R*I] -> xT[R*I, B]   (i-major rows, coalesced lane loads)
//   k_pass<0>   : p=W^T x; acc += p; last CTA: out0 = squash(acc/R), zero acc
//   k_pass<1>   : delta=p.out0; logits=delta; w=exp; acc += w*p; last CTA squash
//   k_pass<2>   : delta=p.out1; logits+=delta; w=exp; acc; last CTA squash->d_out
//
// State is replay-clean: final squash zeroes g_acc and resets the counter.

#define R_DIM 6912
#define B_DIM 64
#define C_DIM 10
#define NCTAS (108 * 10)

typedef unsigned long long u64;

__device__ __align__(16) float g_xT[R_DIM * 8 * B_DIM];         // [r][i][b] 14.2 MB
__device__ __align__(16) float g_logits[C_DIM * R_DIM * B_DIM]; // [c][r][b] 17.7 MB
__device__ __align__(16) float g_acc[C_DIM * B_DIM * 17];       // [c][b][16 o + 1 w]
__device__ __align__(16) float g_out[C_DIM * B_DIM * 16];
__device__ unsigned g_ctr = 0;

// ---- packed f32x2 helpers ----
__device__ __forceinline__ u64 pack2(float lo, float hi) {
    u64 r; asm("mov.b64 %0, {%1, %2};" : "=l"(r) : "f"(lo), "f"(hi)); return r;
}
__device__ __forceinline__ void unpack2(u64 v, float& lo, float& hi) {
    asm("mov.b64 {%0, %1}, %2;" : "=f"(lo), "=f"(hi) : "l"(v));
}
__device__ __forceinline__ u64 fma2(u64 a, u64 b, u64 c) {
    u64 d; asm("fma.rn.f32x2 %0, %1, %2, %3;" : "=l"(d) : "l"(a), "l"(b), "l"(c)); return d;
}
__device__ __forceinline__ u64 add2(u64 a, u64 b) {
    u64 d; asm("add.rn.f32x2 %0, %1, %2;" : "=l"(d) : "l"(a), "l"(b)); return d;
}

// x[b][j] (j = r*8+i, 64 x 55296) -> xT[j][b] (55296 x 64), 32x32 smem tiles
__global__ void k_transpose(const float* __restrict__ x) {
    __shared__ float tile[32][33];
    const int jb = blockIdx.x * 32;
    const int bb = blockIdx.y * 32;
    const int tx = threadIdx.x, ty = threadIdx.y;  // 32 x 8
    #pragma unroll
    for (int k = 0; k < 32; k += 8)
        tile[ty + k][tx] = x[(size_t)(bb + ty + k) * (R_DIM * 8) + jb + tx];
    __syncthreads();
    #pragma unroll
    for (int k = 0; k < 32; k += 8)
        g_xT[(size_t)(jb + ty + k) * B_DIM + bb + tx] = tile[tx][ty + k];
}

// MODE 0: uniform accumulation; 1: delta->store logits->exp-weighted;
// MODE 2: delta + stored logits -> exp-weighted. Last CTA does squash inline.
template <int MODE>
__global__ void __launch_bounds__(128)
k_pass(const float* __restrict__ Wg, float* __restrict__ dout) {
    const int c    = blockIdx.y;
    const int warp = threadIdx.x >> 5;
    const int lane = threadIdx.x & 31;
    const int b0   = lane * 2;

    __shared__ float sacc[4 * B_DIM * 17];
    __shared__ unsigned s_rank;

    u64 outp0[8], outp1[8];
    if (MODE != 0) {
        const u64* ob = reinterpret_cast<const u64*>(g_out + (c * B_DIM + b0) * 16);
        #pragma unroll
        for (int k = 0; k < 8; k++) { outp0[k] = ob[k]; outp1[k] = ob[8 + k]; }
    }

    u64 accp0[8], accp1[8];
    #pragma unroll
    for (int k = 0; k < 8; k++) { accp0[k] = 0ull; accp1[k] = 0ull; }
    float accw0 = 0.0f, accw1 = 0.0f;

    const int r0 = blockIdx.x * 64 + warp;            // warp covers r0, r0+4, ..., r0+60
    const float*  Wbase  = Wg + ((size_t)c * R_DIM + r0) * 128;
    const float2* xbase  = reinterpret_cast<const float2*>(g_xT) + (size_t)r0 * 256 + lane;
    float*        lgbase = g_logits + ((size_t)c * R_DIM + r0) * B_DIM + b0;

    #pragma unroll 1
    for (int k = 0; k < 16; k++) {
        // x: per-i float2 per lane, lane-contiguous (2 lines per load)
        float2 xv[8];
        #pragma unroll
        for (int i = 0; i < 8; i++) xv[i] = xbase[i * 32];

        const ulonglong2* Wp = reinterpret_cast<const ulonglong2*>(Wbase);

        u64 p0[8], p1[8];
        #pragma unroll
        for (int t = 0; t < 8; t++) { p0[t] = 0ull; p1[t] = 0ull; }

        #pragma unroll
        for (int i = 0; i < 8; i++) {
            ulonglong2 q0 = Wp[i * 4 + 0];
            ulonglong2 q1 = Wp[i * 4 + 1];
            ulonglong2 q2 = Wp[i * 4 + 2];
            ulonglong2 q3 = Wp[i * 4 + 3];
            u64 x0 = pack2(xv[i].x, xv[i].x);
            u64 x1 = pack2(xv[i].y, xv[i].y);
            p0[0] = fma2(q0.x, x0, p0[0]); p0[1] = fma2(q0.y, x0, p0[1]);
            p0[2] = fma2(q1.x, x0, p0[2]); p0[3] = fma2(q1.y, x0, p0[3]);
            p0[4] = fma2(q2.x, x0, p0[4]); p0[5] = fma2(q2.y, x0, p0[5]);
            p0[6] = fma2(q3.x, x0, p0[6]); p0[7] = fma2(q3.y, x0, p0[7]);
            p1[0] = fma2(q0.x, x1, p1[0]); p1[1] = fma2(q0.y, x1, p1[1]);
            p1[2] = fma2(q1.x, x1, p1[2]); p1[3] = fma2(q1.y, x1, p1[3]);
            p1[4] = fma2(q2.x, x1, p1[4]); p1[5] = fma2(q2.y, x1, p1[5]);
            p1[6] = fma2(q3.x, x1, p1[6]); p1[7] = fma2(q3.y, x1, p1[7]);
        }

        if (MODE == 0) {
            #pragma unroll
            for (int t = 0; t < 8; t++) {
                accp0[t] = add2(accp0[t], p0[t]);
                accp1[t] = add2(accp1[t], p1[t]);
            }
        } else {
            u64 d0 = 0ull, d1 = 0ull;
            #pragma unroll
            for (int t = 0; t < 8; t++) {
                d0 = fma2(p0[t], outp0[t], d0);
                d1 = fma2(p1[t], outp1[t], d1);
            }
            float lo, hi;
            unpack2(d0, lo, hi); float del0 = lo + hi;
            unpack2(d1, lo, hi); float del1 = lo + hi;

            if (MODE == 2) {
                float2 old = *reinterpret_cast<const float2*>(lgbase);
                del0 += old.x; del1 += old.y;
            }
            if (MODE == 1) {
                *reinterpret_cast<float2*>(lgbase) = make_float2(del0, del1);
            }
            del0 = fminf(del0, 70.0f); del1 = fminf(del1, 70.0f);
            float w0 = __expf(del0), w1 = __expf(del1);
            accw0 += w0; accw1 += w1;
            u64 wd0 = pack2(w0, w0), wd1 = pack2(w1, w1);
            #pragma unroll
            for (int t = 0; t < 8; t++) {
                accp0[t] = fma2(p0[t], wd0, accp0[t]);
                accp1[t] = fma2(p1[t], wd1, accp1[t]);
            }
        }
        Wbase  += 512;   // 4 r * 128 floats
        xbase  += 1024;  // 4 r * 256 float2
        lgbase += 256;   // 4 r * 64 floats
    }

    // per-warp partials -> smem
    float* s0 = sacc + (warp * B_DIM + b0) * 17;
    #pragma unroll
    for (int t = 0; t < 8; t++) {
        float lo, hi;
        unpack2(accp0[t], lo, hi); s0[2 * t] = lo; s0[2 * t + 1] = hi;
        unpack2(accp1[t], lo, hi); s0[17 + 2 * t] = lo; s0[17 + 2 * t + 1] = hi;
    }
    s0[16] = accw0; s0[17 + 16] = accw1;
    __syncthreads();

    for (int idx = threadIdx.x; idx < B_DIM * 17; idx += 128) {
        float v = sacc[idx] + sacc[1088 + idx] + sacc[2 * 1088 + idx] + sacc[3 * 1088 + idx];
        atomicAdd(&g_acc[c * (B_DIM * 17) + idx], v);
    }

    // ---- last CTA of this pass does the squash inline ----
    __threadfence();
    if (threadIdx.x == 0) s_rank = atomicAdd(&g_ctr, 1);
    __syncthreads();
    if (s_rank == NCTAS - 1) {
        for (int pair = threadIdx.x; pair < C_DIM * B_DIM; pair += 128) {
            const float* a = g_acc + pair * 17;
            float invw = (MODE == 0) ? (1.0f / (float)R_DIM) : (1.0f / __ldcg(a + 16));
            float s[16], sq = 0.0f;
            #pragma unroll
            for (int o = 0; o < 16; o++) { s[o] = __ldcg(a + o) * invw; sq += s[o] * s[o]; }
            float coef = sq / ((1.0f + sq) * sqrtf(sq));
            float* dst = (MODE == 2) ? (dout + pair * 16) : (g_out + pair * 16);
            #pragma unroll
            for (int o = 0; o < 16; o++) dst[o] = coef * s[o];
        }
        __syncthreads();  // reads of g_acc done before zeroing
        for (int idx = threadIdx.x; idx < C_DIM * B_DIM * 17; idx += 128) g_acc[idx] = 0.0f;
        if (threadIdx.x == 0) g_ctr = 0;
    }
}

extern "C" void kernel_launch(void* const* d_in, const int* in_sizes, int n_in,
                              void* d_out, int out_size) {
    const float* x = (const float*)d_in[0];          // [64, 6912, 8]
    const float* W = (const float*)d_in[1];          // [10, 6912, 8, 16]
    float* out = (float*)d_out;                      // [10, 64, 1, 1, 16]

    dim3 tgrid(R_DIM * 8 / 32, B_DIM / 32);          // (1728, 2)
    k_transpose<<<tgrid, dim3(32, 8)>>>(x);

    dim3 grid(R_DIM / 64, C_DIM);                    // (108, 10)
    k_pass<0><<<grid, 128>>>(W, nullptr);
    k_pass<1><<<grid, 128>>>(W, nullptr);
    k_pass<2><<<grid, 128>>>(W, out);
}

// round 3
// speedup vs baseline: 1.4395x; 1.4395x over previous
#include <cuda_runtime.h>

// DigitCaps dynamic routing, fused. B=64, R=6912, I=8, C=10, O=16, 3 iters.
//
//   k_transpose : x[B,R,I] -> xT[r][h][b][4]  (float4-transposed, coalesced)
//   k_pass<0>   : p=W^T x; acc += p;                    last CTA: out0=squash
//   k_pass<1>   : w=exp(p.out0); acc += w*p;            last CTA: out1=squash
//   k_pass<2>   : w=exp(p.(out0+out1)); acc += w*p;     last CTA: squash->d_out
//
// logits are never materialized: logit_2 = p.out0 + p.out1 = p.(out0+out1).
// W tiles staged in smem via cp.async; compute reads W via broadcast LDS.
// State replay-clean: final squash zeroes g_acc, resets counter.

#define R_DIM 6912
#define B_DIM 64
#define C_DIM 10
#define R_BLK 32
#define NCTAS ((R_DIM / R_BLK) * C_DIM)   // 2160

typedef unsigned long long u64;

__device__ __align__(16) float g_xT[R_DIM * 2 * B_DIM * 4];   // [r][h][b][4] 14.2 MB
__device__ __align__(16) float g_acc[C_DIM * B_DIM * 17];     // [c][b][16 o + w]
__device__ __align__(16) float g_out[2][C_DIM * B_DIM * 16];  // out0, out1
__device__ unsigned g_ctr = 0;

// ---- packed f32x2 helpers ----
__device__ __forceinline__ u64 pack2(float lo, float hi) {
    u64 r; asm("mov.b64 %0, {%1, %2};" : "=l"(r) : "f"(lo), "f"(hi)); return r;
}
__device__ __forceinline__ void unpack2(u64 v, float& lo, float& hi) {
    asm("mov.b64 {%0, %1}, %2;" : "=f"(lo), "=f"(hi) : "l"(v));
}
__device__ __forceinline__ u64 fma2(u64 a, u64 b, u64 c) {
    u64 d; asm("fma.rn.f32x2 %0, %1, %2, %3;" : "=l"(d) : "l"(a), "l"(b), "l"(c)); return d;
}
__device__ __forceinline__ u64 add2(u64 a, u64 b) {
    u64 d; asm("add.rn.f32x2 %0, %1, %2;" : "=l"(d) : "l"(a), "l"(b)); return d;
}
__device__ __forceinline__ unsigned smem_u32(const void* p) {
    return (unsigned)__cvta_generic_to_shared(p);
}
__device__ __forceinline__ void cp_async16(unsigned saddr, const void* g) {
    asm volatile("cp.async.cg.shared.global [%0], [%1], 16;" :: "r"(saddr), "l"(g));
}

// x as float4 matrix [64][13824] -> [13824][64]; element (b, j) j=r*2+h
__global__ void k_transpose(const float4* __restrict__ x4) {
    __shared__ float4 tile[32][33];
    const int jb = blockIdx.x * 32;
    const int bb = blockIdx.y * 32;
    const int tx = threadIdx.x, ty = threadIdx.y;   // 32 x 8
    #pragma unroll
    for (int k = 0; k < 32; k += 8)
        tile[ty + k][tx] = x4[(size_t)(bb + ty + k) * (R_DIM * 2) + jb + tx];
    __syncthreads();
    float4* out4 = reinterpret_cast<float4*>(g_xT);
    #pragma unroll
    for (int k = 0; k < 32; k += 8)
        out4[(size_t)(jb + ty + k) * B_DIM + bb + tx] = tile[tx][ty + k];
}

// MODE 0: uniform; 1: w=exp(p.out0); 2: w=exp(p.(out0+out1))
template <int MODE>
__global__ void __launch_bounds__(256, 3)
k_pass(const float* __restrict__ Wg, float* __restrict__ dout) {
    const int c      = blockIdx.y;
    const int rblock = blockIdx.x * R_BLK;
    const int warp   = threadIdx.x >> 5;
    const int lane   = threadIdx.x & 31;
    const int rgroup = warp >> 1;                  // 0..3
    const int b      = (warp & 1) * 32 + lane;     // 0..63

    __shared__ float sW[R_BLK * 128];              // 16 KB W tile
    __shared__ float sred[4][B_DIM][17];           // 17.4 KB reduction
    __shared__ unsigned s_rank;

    // --- async-stage this CTA's W tile (contiguous 16 KB) ---
    {
        const char* src = reinterpret_cast<const char*>(Wg + ((size_t)c * R_DIM + rblock) * 128);
        unsigned dst = smem_u32(sW);
        #pragma unroll
        for (int s = 0; s < 4; s++)
            cp_async16(dst + threadIdx.x * 16 + s * 4096, src + threadIdx.x * 16 + s * 4096);
        asm volatile("cp.async.commit_group;");
    }

    // out vector for this thread's b (constant over r)
    u64 ov[8];
    if (MODE == 1) {
        const u64* o0 = reinterpret_cast<const u64*>(g_out[0] + (c * B_DIM + b) * 16);
        #pragma unroll
        for (int t = 0; t < 8; t++) ov[t] = o0[t];
    } else if (MODE == 2) {
        const u64* o0 = reinterpret_cast<const u64*>(g_out[0] + (c * B_DIM + b) * 16);
        const u64* o1 = reinterpret_cast<const u64*>(g_out[1] + (c * B_DIM + b) * 16);
        #pragma unroll
        for (int t = 0; t < 8; t++) ov[t] = add2(o0[t], o1[t]);
    }

    u64 accp[8];
    #pragma unroll
    for (int t = 0; t < 8; t++) accp[t] = 0ull;
    float accw = 0.0f;

    asm volatile("cp.async.wait_group 0;");
    __syncthreads();

    const float4* x4 = reinterpret_cast<const float4*>(g_xT);

    #pragma unroll 1
    for (int k = 0; k < 8; k++) {
        const int rl = rgroup + k * 4;             // local r in 0..31
        const int r  = rblock + rl;

        // x[b][r][0..7] : two float4, lanes coalesced (b fast dim)
        float4 xa = x4[(size_t)(r * 2 + 0) * B_DIM + b];
        float4 xb = x4[(size_t)(r * 2 + 1) * B_DIM + b];
        const float xf[8] = {xa.x, xa.y, xa.z, xa.w, xb.x, xb.y, xb.z, xb.w};

        // W row from smem (broadcast, conflict-free)
        const u64* wp = reinterpret_cast<const u64*>(sW + rl * 128);

        u64 p[8];
        #pragma unroll
        for (int t = 0; t < 8; t++) p[t] = 0ull;
        #pragma unroll
        for (int i = 0; i < 8; i++) {
            u64 xi = pack2(xf[i], xf[i]);
            #pragma unroll
            for (int t = 0; t < 8; t++)
                p[t] = fma2(wp[i * 8 + t], xi, p[t]);
        }

        if (MODE == 0) {
            #pragma unroll
            for (int t = 0; t < 8; t++) accp[t] = add2(accp[t], p[t]);
        } else {
            u64 d = 0ull;
            #pragma unroll
            for (int t = 0; t < 8; t++) d = fma2(p[t], ov[t], d);
            float lo, hi; unpack2(d, lo, hi);
            float del = fminf(lo + hi, 70.0f);
            float w = __expf(del);
            accw += w;
            u64 w2 = pack2(w, w);
            #pragma unroll
            for (int t = 0; t < 8; t++) accp[t] = fma2(p[t], w2, accp[t]);
        }
    }

    // per-thread partials -> smem slot (rgroup, b)
    {
        float* s = sred[rgroup][b];
        #pragma unroll
        for (int t = 0; t < 8; t++) {
            float lo, hi; unpack2(accp[t], lo, hi);
            s[2 * t] = lo; s[2 * t + 1] = hi;
        }
        s[16] = accw;
    }
    __syncthreads();

    // fold 4 rgroups, atomicAdd to global
    for (int idx = threadIdx.x; idx < B_DIM * 17; idx += 256) {
        const int bb = idx / 17, j = idx % 17;
        float v = sred[0][bb][j] + sred[1][bb][j] + sred[2][bb][j] + sred[3][bb][j];
        atomicAdd(&g_acc[c * (B_DIM * 17) + idx], v);
    }

    // ---- last CTA of this pass: squash inline ----
    __threadfence();
    if (threadIdx.x == 0) s_rank = atomicAdd(&g_ctr, 1);
    __syncthreads();
    if (s_rank == NCTAS - 1) {
        for (int pair = threadIdx.x; pair < C_DIM * B_DIM; pair += 256) {
            const float* a = g_acc + pair * 17;
            float invw = (MODE == 0) ? (1.0f / (float)R_DIM) : (1.0f / __ldcg(a + 16));
            float s[16], sq = 0.0f;
            #pragma unroll
            for (int o = 0; o < 16; o++) { s[o] = __ldcg(a + o) * invw; sq += s[o] * s[o]; }
            float coef = sq / ((1.0f + sq) * sqrtf(sq));
            float* dst = (MODE == 2) ? (dout + pair * 16)
                                     : (g_out[MODE] + pair * 16);
            #pragma unroll
            for (int o = 0; o < 16; o++) dst[o] = coef * s[o];
        }
        __syncthreads();
        for (int idx = threadIdx.x; idx < C_DIM * B_DIM * 17; idx += 256) g_acc[idx] = 0.0f;
        if (threadIdx.x == 0) g_ctr = 0;
    }
}

extern "C" void kernel_launch(void* const* d_in, const int* in_sizes, int n_in,
                              void* d_out, int out_size) {
    const float* x = (const float*)d_in[0];          // [64, 6912, 8]
    const float* W = (const float*)d_in[1];          // [10, 6912, 8, 16]
    float* out = (float*)d_out;                      // [10, 64, 1, 1, 16]

    dim3 tgrid(R_DIM * 2 / 32, B_DIM / 32);          // (432, 2)
    k_transpose<<<tgrid, dim3(32, 8)>>>(reinterpret_cast<const float4*>(x));

    dim3 grid(R_DIM / R_BLK, C_DIM);                 // (216, 10)
    k_pass<0><<<grid, 256>>>(W, nullptr);
    k_pass<1><<<grid, 256>>>(W, nullptr);
    k_pass<2><<<grid, 256>>>(W, out);
}

// round 4
// speedup vs baseline: 1.5839x; 1.1003x over previous
#include <cuda_runtime.h>

// DigitCaps dynamic routing, fused. B=64, R=6912, I=8, C=10, O=16, 3 iters.
//
//   k_transpose : x[B,R,I] -> xT[j=r*2+h][b] (float4 transposed)
//   k_pass<0>   : p=W^T x; acc += p;                 last CTA: out0=squash
//   k_pass<1>   : w=exp(p.out0); acc += w*p;         last CTA: out1=squash
//   k_pass<2>   : w=exp(p.(out0+out1)); acc += w*p;  last CTA: squash->d_out
//
// Thread owns (b, b+16) x 8-o half; W read via 16 LDS.128/r-step (amortized
// over 2 b), dot completed with one shfl_xor(16). Replay-clean state.

#define R_DIM 6912
#define B_DIM 64
#define C_DIM 10
#define R_BLK 64
#define NCTAS ((R_DIM / R_BLK) * C_DIM)   // 1080

typedef unsigned long long u64;

__device__ __align__(16) float g_xT[R_DIM * 2 * B_DIM * 4];   // [r*2+h][b] float4
__device__ __align__(16) float g_acc[C_DIM * B_DIM * 16];
__device__ __align__(16) float g_accw[C_DIM * B_DIM];
__device__ __align__(16) float g_out[2][C_DIM * B_DIM * 16];
__device__ unsigned g_ctr = 0;

__device__ __forceinline__ u64 pack2(float lo, float hi) {
    u64 r; asm("mov.b64 %0, {%1, %2};" : "=l"(r) : "f"(lo), "f"(hi)); return r;
}
__device__ __forceinline__ void unpack2(u64 v, float& lo, float& hi) {
    asm("mov.b64 {%0, %1}, %2;" : "=f"(lo), "=f"(hi) : "l"(v));
}
__device__ __forceinline__ u64 fma2(u64 a, u64 b, u64 c) {
    u64 d; asm("fma.rn.f32x2 %0, %1, %2, %3;" : "=l"(d) : "l"(a), "l"(b), "l"(c)); return d;
}
__device__ __forceinline__ u64 add2(u64 a, u64 b) {
    u64 d; asm("add.rn.f32x2 %0, %1, %2;" : "=l"(d) : "l"(a), "l"(b)); return d;
}
__device__ __forceinline__ unsigned smem_u32(const void* p) {
    return (unsigned)__cvta_generic_to_shared(p);
}
__device__ __forceinline__ void cp_async16(unsigned saddr, const void* g) {
    asm volatile("cp.async.cg.shared.global [%0], [%1], 16;" :: "r"(saddr), "l"(g));
}

// x as float4 matrix [64][13824] -> [13824][64]
__global__ void k_transpose(const float4* __restrict__ x4) {
    __shared__ float4 tile[32][33];
    const int jb = blockIdx.x * 32;
    const int bb = blockIdx.y * 32;
    const int tx = threadIdx.x, ty = threadIdx.y;   // 32 x 8
    #pragma unroll
    for (int k = 0; k < 32; k += 8)
        tile[ty + k][tx] = x4[(size_t)(bb + ty + k) * (R_DIM * 2) + jb + tx];
    __syncthreads();
    float4* out4 = reinterpret_cast<float4*>(g_xT);
    #pragma unroll
    for (int k = 0; k < 32; k += 8)
        out4[(size_t)(jb + ty + k) * B_DIM + bb + tx] = tile[tx][ty + k];
}

// MODE 0: uniform; 1: w=exp(p.out0); 2: w=exp(p.(out0+out1))
template <int MODE>
__global__ void __launch_bounds__(256, 3)
k_pass(const float* __restrict__ Wg, float* __restrict__ dout) {
    const int c      = blockIdx.y;
    const int rblock = blockIdx.x * R_BLK;
    const int tid    = threadIdx.x;
    const int warp   = tid >> 5;
    const int lane   = tid & 31;
    const int rgroup = warp >> 1;                 // 0..3, each covers 16 r
    const int bhalf  = warp & 1;
    const int oh     = lane >> 4;                 // o-half: 0 or 1
    const int bq     = lane & 15;
    const int b0     = bhalf * 32 + bq;           // owns b0 and b0+16
    const int b1     = b0 + 16;

    __shared__ float sW[R_BLK * 128];             // 32 KB
    __shared__ float sredP[4][B_DIM][16];         // 16 KB
    __shared__ float sredW[4][B_DIM];
    __shared__ unsigned s_rank;

    // --- stage W tile (contiguous 32 KB) ---
    {
        const char* src = reinterpret_cast<const char*>(Wg + ((size_t)c * R_DIM + rblock) * 128);
        unsigned dst = smem_u32(sW);
        #pragma unroll
        for (int s = 0; s < 8; s++)
            cp_async16(dst + tid * 16 + s * 4096, src + tid * 16 + s * 4096);
        asm volatile("cp.async.commit_group;");
    }

    // out-half vectors for b0, b1 (constant over r)
    u64 ov0[4], ov1[4];
    if (MODE != 0) {
        const u64* p00 = reinterpret_cast<const u64*>(g_out[0] + (c * B_DIM + b0) * 16 + oh * 8);
        const u64* p01 = reinterpret_cast<const u64*>(g_out[0] + (c * B_DIM + b1) * 16 + oh * 8);
        #pragma unroll
        for (int t = 0; t < 4; t++) { ov0[t] = p00[t]; ov1[t] = p01[t]; }
        if (MODE == 2) {
            const u64* p10 = reinterpret_cast<const u64*>(g_out[1] + (c * B_DIM + b0) * 16 + oh * 8);
            const u64* p11 = reinterpret_cast<const u64*>(g_out[1] + (c * B_DIM + b1) * 16 + oh * 8);
            #pragma unroll
            for (int t = 0; t < 4; t++) { ov0[t] = add2(ov0[t], p10[t]); ov1[t] = add2(ov1[t], p11[t]); }
        }
    }

    u64 acc0[4], acc1[4];
    #pragma unroll
    for (int t = 0; t < 4; t++) { acc0[t] = 0ull; acc1[t] = 0ull; }
    float accw0 = 0.0f, accw1 = 0.0f;

    asm volatile("cp.async.wait_group 0;");
    __syncthreads();

    const float4* x4 = reinterpret_cast<const float4*>(g_xT);

    #pragma unroll 1
    for (int k = 0; k < 16; k++) {
        const int rl = rgroup * 16 + k;
        const int r  = rblock + rl;

        // x[b][r][0..7] for b0, b1
        float4 xa0 = x4[(size_t)(r * 2 + 0) * B_DIM + b0];
        float4 xb0 = x4[(size_t)(r * 2 + 1) * B_DIM + b0];
        float4 xa1 = x4[(size_t)(r * 2 + 0) * B_DIM + b1];
        float4 xb1 = x4[(size_t)(r * 2 + 1) * B_DIM + b1];
        const float xf0[8] = {xa0.x, xa0.y, xa0.z, xa0.w, xb0.x, xb0.y, xb0.z, xb0.w};
        const float xf1[8] = {xa1.x, xa1.y, xa1.z, xa1.w, xb1.x, xb1.y, xb1.z, xb1.w};

        // W half-row: per i, 8 floats at [rl][i][oh*8]  (2 LDS.128)
        const ulonglong2* wp = reinterpret_cast<const ulonglong2*>(sW + rl * 128 + oh * 8);

        u64 p0[4], p1[4];
        #pragma unroll
        for (int t = 0; t < 4; t++) { p0[t] = 0ull; p1[t] = 0ull; }

        #pragma unroll
        for (int i = 0; i < 8; i++) {
            ulonglong2 wA = wp[i * 4 + 0];   // o-half floats 0..3
            ulonglong2 wB = wp[i * 4 + 1];   // o-half floats 4..7
            u64 xx0 = pack2(xf0[i], xf0[i]);
            u64 xx1 = pack2(xf1[i], xf1[i]);
            p0[0] = fma2(wA.x, xx0, p0[0]); p0[1] = fma2(wA.y, xx0, p0[1]);
            p0[2] = fma2(wB.x, xx0, p0[2]); p0[3] = fma2(wB.y, xx0, p0[3]);
            p1[0] = fma2(wA.x, xx1, p1[0]); p1[1] = fma2(wA.y, xx1, p1[1]);
            p1[2] = fma2(wB.x, xx1, p1[2]); p1[3] = fma2(wB.y, xx1, p1[3]);
        }

        if (MODE == 0) {
            #pragma unroll
            for (int t = 0; t < 4; t++) {
                acc0[t] = add2(acc0[t], p0[t]);
                acc1[t] = add2(acc1[t], p1[t]);
            }
        } else {
            u64 d0 = 0ull, d1 = 0ull;
            #pragma unroll
            for (int t = 0; t < 4; t++) {
                d0 = fma2(p0[t], ov0[t], d0);
                d1 = fma2(p1[t], ov1[t], d1);
            }
            float lo, hi;
            unpack2(d0, lo, hi); float del0 = lo + hi;
            unpack2(d1, lo, hi); float del1 = lo + hi;
            // complete 16-o dot across the two o-half lanes
            del0 += __shfl_xor_sync(0xffffffffu, del0, 16);
            del1 += __shfl_xor_sync(0xffffffffu, del1, 16);
            del0 = fminf(del0, 70.0f); del1 = fminf(del1, 70.0f);
            float w0 = __expf(del0), w1 = __expf(del1);
            accw0 += w0; accw1 += w1;
            u64 w20 = pack2(w0, w0), w21 = pack2(w1, w1);
            #pragma unroll
            for (int t = 0; t < 4; t++) {
                acc0[t] = fma2(p0[t], w20, acc0[t]);
                acc1[t] = fma2(p1[t], w21, acc1[t]);
            }
        }
    }

    // partials -> smem
    {
        float2* s0 = reinterpret_cast<float2*>(&sredP[rgroup][b0][oh * 8]);
        float2* s1 = reinterpret_cast<float2*>(&sredP[rgroup][b1][oh * 8]);
        #pragma unroll
        for (int t = 0; t < 4; t++) {
            float lo, hi;
            unpack2(acc0[t], lo, hi); s0[t] = make_float2(lo, hi);
            unpack2(acc1[t], lo, hi); s1[t] = make_float2(lo, hi);
        }
        if (MODE != 0 && oh == 0) { sredW[rgroup][b0] = accw0; sredW[rgroup][b1] = accw1; }
    }
    __syncthreads();

    // fold 4 rgroups -> global atomics
    for (int idx = tid; idx < B_DIM * 16; idx += 256) {
        const int bb = idx >> 4, o = idx & 15;
        float v = sredP[0][bb][o] + sredP[1][bb][o] + sredP[2][bb][o] + sredP[3][bb][o];
        atomicAdd(&g_acc[c * (B_DIM * 16) + idx], v);
    }
    if (MODE != 0 && tid < B_DIM) {
        float v = sredW[0][tid] + sredW[1][tid] + sredW[2][tid] + sredW[3][tid];
        atomicAdd(&g_accw[c * B_DIM + tid], v);
    }

    // ---- last CTA: squash inline ----
    __threadfence();
    if (tid == 0) s_rank = atomicAdd(&g_ctr, 1);
    __syncthreads();
    if (s_rank == NCTAS - 1) {
        for (int pair = tid; pair < C_DIM * B_DIM; pair += 256) {
            const float* a = g_acc + pair * 16;
            float invw = (MODE == 0) ? (1.0f / (float)R_DIM) : (1.0f / __ldcg(&g_accw[pair]));
            float s[16], sq = 0.0f;
            #pragma unroll
            for (int o = 0; o < 16; o++) { s[o] = __ldcg(a + o) * invw; sq += s[o] * s[o]; }
            float coef = sq / ((1.0f + sq) * sqrtf(sq));
            float* dst = (MODE == 2) ? (dout + pair * 16) : (g_out[MODE] + pair * 16);
            #pragma unroll
            for (int o = 0; o < 16; o++) dst[o] = coef * s[o];
        }
        __syncthreads();
        for (int idx = tid; idx < C_DIM * B_DIM * 16; idx += 256) g_acc[idx] = 0.0f;
        for (int idx = tid; idx < C_DIM * B_DIM; idx += 256) g_accw[idx] = 0.0f;
        if (tid == 0) g_ctr = 0;
    }
}

extern "C" void kernel_launch(void* const* d_in, const int* in_sizes, int n_in,
                              void* d_out, int out_size) {
    const float* x = (const float*)d_in[0];          // [64, 6912, 8]
    const float* W = (const float*)d_in[1];          // [10, 6912, 8, 16]
    float* out = (float*)d_out;                      // [10, 64, 1, 1, 16]

    dim3 tgrid(R_DIM * 2 / 32, B_DIM / 32);          // (432, 2)
    k_transpose<<<tgrid, dim3(32, 8)>>>(reinterpret_cast<const float4*>(x));

    dim3 grid(R_DIM / R_BLK, C_DIM);                 // (108, 10)
    k_pass<0><<<grid, 256>>>(W, nullptr);
    k_pass<1><<<grid, 256>>>(W, nullptr);
    k_pass<2><<<grid, 256>>>(W, out);
}